// round 12
// baseline (speedup 1.0000x reference)
#include <cuda_runtime.h>
#include <cuda_fp16.h>
#include <cuda_bf16.h>
#include <stdint.h>

#define N_RAYS   4096
#define N_INTERS 1536
#define NSAMP    1535          // N_INTERS - 1
#define RESV     128
#define CHAN     28
#define NVOX     (128*128*128)
#define CHSTRIDE NVOX
#define TR_BLOCKS (NVOX / 256)   // 8192 transpose blocks
#define GCHUNKS  24              // 24*64 = 1536 >= max cnt

__device__ int    g_ray_count[N_RAYS];
__device__ int    g_ray_base[N_RAYS + 1];   // +1 sentinel = nm
struct RayPack { float4 o_start; float4 d; };
__device__ RayPack g_raypack[N_RAYS];

// channel-last fp16 grid: voxel record = 28 halves + 4 pad = 64B = 4x uint4
__device__ uint4 g_data64[(size_t)NVOX * 4];

// --- mask-critical math: must be bit-stable under --use_fast_math ---
__device__ __forceinline__ float voxel_len() {
    return __fdiv_rn(__fsqrt_rn(27.0f), 1536.0f);
}

__device__ __forceinline__ float compute_start(float ox, float oy, float oz,
                                               float dx, float dy, float dz) {
    float px = __fdiv_rn(1.5f - ox, dx);
    float py = __fdiv_rn(1.5f - oy, dy);
    float pz = __fdiv_rn(1.5f - oz, dz);
    float nx = __fdiv_rn(-1.5f - ox, dx);
    float ny = __fdiv_rn(-1.5f - oy, dy);
    float nz = __fdiv_rn(-1.5f - oz, dz);
    float ix = fminf(px, nx);
    float iy = fminf(py, ny);
    float iz = fminf(pz, nz);
    float s  = fmaxf(fmaxf(ix, iy), iz);
    return fminf(fmaxf(s, 0.2f), 6.0f);
}

__device__ __forceinline__ float sample_t(float start, int j) {
    return __fadd_rn(start, __fmul_rn((float)j, voxel_len()));
}

__device__ __forceinline__ void point_at(float start, int j,
                                         float ox, float oy, float oz,
                                         float dx, float dy, float dz,
                                         float& px, float& py, float& pz) {
    float t = sample_t(start, j);
    px = __fadd_rn(ox, __fmul_rn(t, dx));
    py = __fadd_rn(oy, __fmul_rn(t, dy));
    pz = __fadd_rn(oz, __fmul_rn(t, dz));
}

__device__ __forceinline__ bool in_box(float px, float py, float pz) {
    return (-1.5f < px) & (px < 1.5f) &
           (-1.5f < py) & (py < 1.5f) &
           (-1.5f < pz) & (pz < 1.5f);
}

// unpack 8 halves (uint4) into 8 floats
__device__ __forceinline__ void unpack8(uint4 u, float* f) {
    float2 t;
    t = __half22float2(*reinterpret_cast<__half2*>(&u.x)); f[0]=t.x; f[1]=t.y;
    t = __half22float2(*reinterpret_cast<__half2*>(&u.y)); f[2]=t.x; f[3]=t.y;
    t = __half22float2(*reinterpret_cast<__half2*>(&u.z)); f[4]=t.x; f[5]=t.y;
    t = __half22float2(*reinterpret_cast<__half2*>(&u.w)); f[6]=t.x; f[7]=t.y;
}

// ============ Kernel 0 (fused): transpose->fp16  +  mask/count/intersections ========
__global__ void __launch_bounds__(256)
k_pre(const float* __restrict__ data,
      const float* __restrict__ rays_o, const float* __restrict__ rays_d,
      float* __restrict__ mask_out, float* __restrict__ intr_out) {
    __shared__ float tile[28][257];
    int tid = threadIdx.x;

    if (blockIdx.x < TR_BLOCKS) {
        // -------- transpose path: 256 voxels per block --------
        int v0 = blockIdx.x * 256;
        #pragma unroll
        for (int c = 0; c < 28; c++)
            tile[c][tid] = __ldg(data + (size_t)c * CHSTRIDE + v0 + tid);
        __syncthreads();
        uint2* out = (uint2*)g_data64;   // voxel record = 8 uint2, write all 8 (full 64B lines)
        #pragma unroll
        for (int k = 0; k < 8; k++) {
            int l  = k * 256 + tid;      // [0, 2048)
            int v  = l >> 3;
            int c4 = l & 7;              // uint2 index 0..7 (7 = zero pad)
            uint2 u;
            if (c4 < 7) {
                __half2 h0 = __floats2half2_rn(tile[4*c4+0][v], tile[4*c4+1][v]);
                __half2 h1 = __floats2half2_rn(tile[4*c4+2][v], tile[4*c4+3][v]);
                u.x = *reinterpret_cast<unsigned*>(&h0);
                u.y = *reinterpret_cast<unsigned*>(&h1);
            } else {
                u.x = 0u; u.y = 0u;
            }
            out[(size_t)(v0 + v) * 8 + c4] = u;
        }
        return;
    }

    // -------- mask path --------
    int ray = blockIdx.x - TR_BLOCKS;
    float ox = rays_o[ray*3+0], oy = rays_o[ray*3+1], oz = rays_o[ray*3+2];
    float dx = rays_d[ray*3+0], dy = rays_d[ray*3+1], dz = rays_d[ray*3+2];
    float start = compute_start(ox, oy, oz, dx, dy, dz);

    if (tid == 0) {
        RayPack rp;
        rp.o_start = make_float4(ox, oy, oz, start);
        rp.d       = make_float4(dx, dy, dz, 0.0f);
        g_raypack[ray] = rp;
    }

    for (int j = tid; j < N_INTERS; j += 256)
        __stcs(intr_out + (size_t)ray * N_INTERS + j, sample_t(start, j));

    int cnt = 0;
    for (int j = tid; j < NSAMP; j += 256) {
        float px, py, pz;
        point_at(start, j, ox, oy, oz, dx, dy, dz, px, py, pz);
        bool m = in_box(px, py, pz);
        __stcs(mask_out + (size_t)ray * NSAMP + j, m ? 1.0f : 0.0f);
        cnt += m;
    }
    int* sh = (int*)tile;  // reuse smem
    for (int o = 16; o > 0; o >>= 1) cnt += __shfl_down_sync(0xffffffffu, cnt, o);
    if ((tid & 31) == 0) sh[tid >> 5] = cnt;
    __syncthreads();
    if (tid == 0) {
        int s = 0;
        #pragma unroll
        for (int w = 0; w < 8; w++) s += sh[w];
        g_ray_count[ray] = s;
    }
}

// =====================  Kernel 2: exclusive scan over 4096 ray counts ================
__global__ void __launch_bounds__(1024)
k_scan() {
    __shared__ int sh[1024];
    int tid = threadIdx.x;
    int c0 = g_ray_count[tid*4+0];
    int c1 = g_ray_count[tid*4+1];
    int c2 = g_ray_count[tid*4+2];
    int c3 = g_ray_count[tid*4+3];
    int tot = c0 + c1 + c2 + c3;
    sh[tid] = tot;
    __syncthreads();
    for (int off = 1; off < 1024; off <<= 1) {
        int v = (tid >= off) ? sh[tid - off] : 0;
        __syncthreads();
        sh[tid] += v;
        __syncthreads();
    }
    int excl = sh[tid] - tot;
    g_ray_base[tid*4+0] = excl;
    g_ray_base[tid*4+1] = excl + c0;
    g_ray_base[tid*4+2] = excl + c0 + c1;
    g_ray_base[tid*4+3] = excl + c0 + c1 + c2;
    if (tid == 1023) g_ray_base[N_RAYS] = sh[1023];   // sentinel
}

// =====================  Kernel 3: 2D-grid gather, 4 lanes per sample, fp16 grid ======
// block (chunk cx, ray): samples j in [cx*64, cx*64+64); oidx = base[ray] + j.
__global__ void __launch_bounds__(256)
k_gather(float* __restrict__ data_out, float* __restrict__ sub_out) {
    int ray = blockIdx.y;
    int base = __ldg(&g_ray_base[ray]);
    int cnt  = __ldg(&g_ray_base[ray + 1]) - base;

    int tid = threadIdx.x;
    int j   = blockIdx.x * 64 + (tid >> 2);
    int sub = tid & 3;
    if (j >= cnt) return;
    int s = base + j;

    float4 osr = __ldg(&g_raypack[ray].o_start);
    float4 dd  = __ldg(&g_raypack[ray].d);

    float px, py, pz;
    point_at(osr.w, j, osr.x, osr.y, osr.z, dd.x, dd.y, dd.z, px, py, pz);

    const float INV = 0.66666668653f;  // float(2/3)
    float nx = (px + 1.5f) * INV - 1.0f;
    float ny = (py + 1.5f) * INV - 1.0f;
    float nz = (pz + 1.5f) * INV - 1.0f;

    // trilinear coords
    float x = (nx + 1.0f) * 63.5f;
    float y = (ny + 1.0f) * 63.5f;
    float z = (nz + 1.0f) * 63.5f;
    float x0f = floorf(x), y0f = floorf(y), z0f = floorf(z);
    float fx = x - x0f, fy = y - y0f, fz = z - z0f;
    int ix0 = min(max((int)x0f, 0), 127);
    int iy0 = min(max((int)y0f, 0), 127);
    int iz0 = min(max((int)z0f, 0), 127);
    int ix1 = min(ix0 + 1, 127);
    int iy1 = min(iy0 + 1, 127);
    int iz1 = min(iz0 + 1, 127);

    float gxc = 1.0f - fx, gyc = 1.0f - fy, gzc = 1.0f - fz;
    float w000 = gzc * gyc * gxc;
    float w001 = gzc * gyc * fx;
    float w010 = gzc * fy  * gxc;
    float w011 = gzc * fy  * fx;
    float w100 = fz  * gyc * gxc;
    float w101 = fz  * gyc * fx;
    float w110 = fz  * fy  * gxc;
    float w111 = fz  * fy  * fx;

    int b00 = (iz0 * RESV + iy0) * RESV;
    int b01 = (iz0 * RESV + iy1) * RESV;
    int b10 = (iz1 * RESV + iy0) * RESV;
    int b11 = (iz1 * RESV + iy1) * RESV;

    const uint4* G = g_data64;
    uint4 a = __ldg(G + (((size_t)(b00 + ix0)) << 2) + sub);
    uint4 b = __ldg(G + (((size_t)(b00 + ix1)) << 2) + sub);
    uint4 c = __ldg(G + (((size_t)(b01 + ix0)) << 2) + sub);
    uint4 d = __ldg(G + (((size_t)(b01 + ix1)) << 2) + sub);
    uint4 e = __ldg(G + (((size_t)(b10 + ix0)) << 2) + sub);
    uint4 f = __ldg(G + (((size_t)(b10 + ix1)) << 2) + sub);
    uint4 h = __ldg(G + (((size_t)(b11 + ix0)) << 2) + sub);
    uint4 i = __ldg(G + (((size_t)(b11 + ix1)) << 2) + sub);

    float fa[8], fb[8], fc[8], fd[8], fe[8], ff[8], fh[8], fi[8];
    unpack8(a, fa); unpack8(b, fb); unpack8(c, fc); unpack8(d, fd);
    unpack8(e, fe); unpack8(f, ff); unpack8(h, fh); unpack8(i, fi);

    float r[8];
    #pragma unroll
    for (int k = 0; k < 8; k++) {
        r[k] = w000*fa[k] + w001*fb[k] + w010*fc[k] + w011*fd[k]
             + w100*fe[k] + w101*ff[k] + w110*fh[k] + w111*fi[k];
    }

    float4* op = (float4*)(data_out + (size_t)s * CHAN);
    __stcs(op + sub*2, make_float4(r[0], r[1], r[2], r[3]));
    if (sub < 3) {
        __stcs(op + sub*2 + 1, make_float4(r[4], r[5], r[6], r[7]));
    } else {
        // sub == 3: also write sub_pts
        float gx = (nx + 1.0f) * 64.0f;
        float gy = (ny + 1.0f) * 64.0f;
        float gz = (nz + 1.0f) * 64.0f;
        float gix = fminf(fmaxf(floorf(gx), 0.0f), 127.0f);
        float giy = fminf(fmaxf(floorf(gy), 0.0f), 127.0f);
        float giz = fminf(fmaxf(floorf(gz), 0.0f), 127.0f);
        __stcs(sub_out + (size_t)s*3+0, gx - gix);
        __stcs(sub_out + (size_t)s*3+1, gy - giy);
        __stcs(sub_out + (size_t)s*3+2, gz - giz);
    }
}

extern "C" void kernel_launch(void* const* d_in, const int* in_sizes, int n_in,
                              void* d_out, int out_size) {
    const float* rays_o = (const float*)d_in[0];
    const float* rays_d = (const float*)d_in[1];
    const float* data   = (const float*)d_in[2];
    float* out = (float*)d_out;

    const long long MASK_N = (long long)N_RAYS * NSAMP;    // 6,287,360
    const long long INTR_N = (long long)N_RAYS * N_INTERS; // 6,291,456
    long long nm = ((long long)out_size - MASK_N - INTR_N) / 31LL;

    float* data_out = out;
    float* mask_out = out + nm * CHAN;
    float* intr_out = mask_out + MASK_N;
    float* sub_out  = intr_out + INTR_N;

    k_pre<<<TR_BLOCKS + N_RAYS, 256>>>(data, rays_o, rays_d, mask_out, intr_out);
    k_scan<<<1, 1024>>>();

    dim3 ggrid(GCHUNKS, N_RAYS);
    k_gather<<<ggrid, 256>>>(data_out, sub_out);
}

// round 13
// speedup vs baseline: 1.1559x; 1.1559x over previous
#include <cuda_runtime.h>
#include <cuda_fp16.h>
#include <cuda_bf16.h>
#include <stdint.h>

#define N_RAYS   4096
#define N_INTERS 1536
#define NSAMP    1535          // N_INTERS - 1
#define RESV     128
#define CHAN     28
#define NVOX     (128*128*128)
#define CHSTRIDE NVOX
#define TR_BLOCKS (NVOX / 256)   // 8192 transpose blocks

__device__ int    g_ray_base[N_RAYS + 1];   // exclusive scan + sentinel nm
__device__ int    g_map[(size_t)N_RAYS * NSAMP];   // oidx -> (ray<<11)|j
struct RayPack { float4 o_start; float4 d; };
__device__ RayPack g_raypack[N_RAYS];

// channel-last fp16 grid: voxel record = 28 halves + 4 pad = 64B = 4x uint4
__device__ uint4 g_data64[(size_t)NVOX * 4];

// --- mask-critical math: must be bit-stable under --use_fast_math ---
__device__ __forceinline__ float voxel_len() {
    return __fdiv_rn(__fsqrt_rn(27.0f), 1536.0f);
}

__device__ __forceinline__ float compute_start(float ox, float oy, float oz,
                                               float dx, float dy, float dz) {
    float px = __fdiv_rn(1.5f - ox, dx);
    float py = __fdiv_rn(1.5f - oy, dy);
    float pz = __fdiv_rn(1.5f - oz, dz);
    float nx = __fdiv_rn(-1.5f - ox, dx);
    float ny = __fdiv_rn(-1.5f - oy, dy);
    float nz = __fdiv_rn(-1.5f - oz, dz);
    float ix = fminf(px, nx);
    float iy = fminf(py, ny);
    float iz = fminf(pz, nz);
    float s  = fmaxf(fmaxf(ix, iy), iz);
    return fminf(fmaxf(s, 0.2f), 6.0f);
}

__device__ __forceinline__ float sample_t(float start, int j) {
    return __fadd_rn(start, __fmul_rn((float)j, voxel_len()));
}

__device__ __forceinline__ void point_at(float start, int j,
                                         float ox, float oy, float oz,
                                         float dx, float dy, float dz,
                                         float& px, float& py, float& pz) {
    float t = sample_t(start, j);
    px = __fadd_rn(ox, __fmul_rn(t, dx));
    py = __fadd_rn(oy, __fmul_rn(t, dy));
    pz = __fadd_rn(oz, __fmul_rn(t, dz));
}

__device__ __forceinline__ bool in_box(float px, float py, float pz) {
    return (-1.5f < px) & (px < 1.5f) &
           (-1.5f < py) & (py < 1.5f) &
           (-1.5f < pz) & (pz < 1.5f);
}

// exact mask predicate for (ray params, j) -- bit-identical to the old mask pass
__device__ __forceinline__ bool pred(float start, int j,
                                     float ox, float oy, float oz,
                                     float dx, float dy, float dz) {
    float px, py, pz;
    point_at(start, j, ox, oy, oz, dx, dy, dz, px, py, pz);
    return in_box(px, py, pz);
}

// unpack 8 halves (uint4) into 8 floats
__device__ __forceinline__ void unpack8(uint4 u, float* f) {
    float2 t;
    t = __half22float2(*reinterpret_cast<__half2*>(&u.x)); f[0]=t.x; f[1]=t.y;
    t = __half22float2(*reinterpret_cast<__half2*>(&u.y)); f[2]=t.x; f[3]=t.y;
    t = __half22float2(*reinterpret_cast<__half2*>(&u.z)); f[4]=t.x; f[5]=t.y;
    t = __half22float2(*reinterpret_cast<__half2*>(&u.w)); f[6]=t.x; f[7]=t.y;
}

// ============ Kernel 1: per-ray start + exact cnt (analytic + refine) + scan =========
__global__ void __launch_bounds__(1024)
k_scan2(const float* __restrict__ rays_o, const float* __restrict__ rays_d) {
    __shared__ int sh[1024];
    int tid = threadIdx.x;
    int cnts[4];

    #pragma unroll
    for (int i = 0; i < 4; i++) {
        int ray = tid * 4 + i;
        float ox = rays_o[ray*3+0], oy = rays_o[ray*3+1], oz = rays_o[ray*3+2];
        float dx = rays_d[ray*3+0], dy = rays_d[ray*3+1], dz = rays_d[ray*3+2];
        float start = compute_start(ox, oy, oz, dx, dy, dz);

        RayPack rp;
        rp.o_start = make_float4(ox, oy, oz, start);
        rp.d       = make_float4(dx, dy, dz, 0.0f);
        g_raypack[ray] = rp;

        // analytic exit-time estimate (tolerant math; exact refinement below)
        float te = 1e30f;
        if (dx > 0.0f) te = fminf(te, (1.5f - ox) / dx);
        else if (dx < 0.0f) te = fminf(te, (-1.5f - ox) / dx);
        if (dy > 0.0f) te = fminf(te, (1.5f - oy) / dy);
        else if (dy < 0.0f) te = fminf(te, (-1.5f - oy) / dy);
        if (dz > 0.0f) te = fminf(te, (1.5f - oz) / dz);
        else if (dz < 0.0f) te = fminf(te, (-1.5f - oz) / dz);

        float fj = (te - start) / voxel_len();
        int j = (fj < 0.0f) ? 0 : ((fj > (float)NSAMP) ? NSAMP : (int)fj);
        // exact refinement using the bit-exact predicate (mask is a j-prefix)
        while (j > 0 && !pred(start, j - 1, ox, oy, oz, dx, dy, dz)) j--;
        while (j < NSAMP && pred(start, j, ox, oy, oz, dx, dy, dz)) j++;
        cnts[i] = j;
    }

    int tot = cnts[0] + cnts[1] + cnts[2] + cnts[3];
    sh[tid] = tot;
    __syncthreads();
    for (int off = 1; off < 1024; off <<= 1) {
        int v = (tid >= off) ? sh[tid - off] : 0;
        __syncthreads();
        sh[tid] += v;
        __syncthreads();
    }
    int excl = sh[tid] - tot;
    g_ray_base[tid*4+0] = excl;
    g_ray_base[tid*4+1] = excl + cnts[0];
    g_ray_base[tid*4+2] = excl + cnts[0] + cnts[1];
    g_ray_base[tid*4+3] = excl + cnts[0] + cnts[1] + cnts[2];
    if (tid == 1023) g_ray_base[N_RAYS] = sh[1023];   // sentinel = nm
}

// ============ Kernel 2 (fused): transpose->fp16  +  build_map =======================
__global__ void __launch_bounds__(256)
k_trmap(const float* __restrict__ data) {
    int tid = threadIdx.x;

    if (blockIdx.x < TR_BLOCKS) {
        __shared__ float tile[28][257];
        int v0 = blockIdx.x * 256;
        #pragma unroll
        for (int c = 0; c < 28; c++)
            tile[c][tid] = __ldg(data + (size_t)c * CHSTRIDE + v0 + tid);
        __syncthreads();
        uint2* out = (uint2*)g_data64;   // 8 uint2 per voxel, write all 8 (full 64B lines)
        #pragma unroll
        for (int k = 0; k < 8; k++) {
            int l  = k * 256 + tid;
            int v  = l >> 3;
            int c4 = l & 7;
            uint2 u;
            if (c4 < 7) {
                __half2 h0 = __floats2half2_rn(tile[4*c4+0][v], tile[4*c4+1][v]);
                __half2 h1 = __floats2half2_rn(tile[4*c4+2][v], tile[4*c4+3][v]);
                u.x = *reinterpret_cast<unsigned*>(&h0);
                u.y = *reinterpret_cast<unsigned*>(&h1);
            } else {
                u.x = 0u; u.y = 0u;
            }
            out[(size_t)(v0 + v) * 8 + c4] = u;
        }
        return;
    }

    // build_map path
    int ray  = blockIdx.x - TR_BLOCKS;
    int base = __ldg(&g_ray_base[ray]);
    int cnt  = __ldg(&g_ray_base[ray + 1]) - base;
    int tag  = ray << 11;
    for (int j = tid; j < cnt; j += 256)
        g_map[base + j] = tag | j;
}

// ============ Kernel 3 (fused): mask/intersections blocks + flat gather ==============
__global__ void __launch_bounds__(256)
k_gather(float* __restrict__ data_out, float* __restrict__ sub_out,
         float* __restrict__ mask_out, float* __restrict__ intr_out, int nm) {
    int tid = threadIdx.x;

    if (blockIdx.x < N_RAYS) {
        // -------- mask + intersections path (pure stores; cnt from scan) --------
        int ray  = blockIdx.x;
        int base = __ldg(&g_ray_base[ray]);
        int cnt  = __ldg(&g_ray_base[ray + 1]) - base;
        float start = __ldg(&g_raypack[ray].o_start).w;
        for (int j = tid; j < N_INTERS; j += 256)
            __stcs(intr_out + (size_t)ray * N_INTERS + j, sample_t(start, j));
        for (int j = tid; j < NSAMP; j += 256)
            __stcs(mask_out + (size_t)ray * NSAMP + j, (j < cnt) ? 1.0f : 0.0f);
        return;
    }

    // -------- flat gather: 4 lanes per sample (R9-proven body) --------
    int gt = (blockIdx.x - N_RAYS) * 256 + tid;
    int s   = gt >> 2;
    int sub = gt & 3;
    if (s >= nm) return;

    int info = __ldg(&g_map[s]);
    int ray = info >> 11;
    int j   = info & 2047;

    float4 osr = __ldg(&g_raypack[ray].o_start);
    float4 dd  = __ldg(&g_raypack[ray].d);

    float px, py, pz;
    point_at(osr.w, j, osr.x, osr.y, osr.z, dd.x, dd.y, dd.z, px, py, pz);

    const float INV = 0.66666668653f;  // float(2/3)
    float nx = (px + 1.5f) * INV - 1.0f;
    float ny = (py + 1.5f) * INV - 1.0f;
    float nz = (pz + 1.5f) * INV - 1.0f;

    float x = (nx + 1.0f) * 63.5f;
    float y = (ny + 1.0f) * 63.5f;
    float z = (nz + 1.0f) * 63.5f;
    float x0f = floorf(x), y0f = floorf(y), z0f = floorf(z);
    float fx = x - x0f, fy = y - y0f, fz = z - z0f;
    int ix0 = min(max((int)x0f, 0), 127);
    int iy0 = min(max((int)y0f, 0), 127);
    int iz0 = min(max((int)z0f, 0), 127);
    int ix1 = min(ix0 + 1, 127);
    int iy1 = min(iy0 + 1, 127);
    int iz1 = min(iz0 + 1, 127);

    float gxc = 1.0f - fx, gyc = 1.0f - fy, gzc = 1.0f - fz;
    float w000 = gzc * gyc * gxc;
    float w001 = gzc * gyc * fx;
    float w010 = gzc * fy  * gxc;
    float w011 = gzc * fy  * fx;
    float w100 = fz  * gyc * gxc;
    float w101 = fz  * gyc * fx;
    float w110 = fz  * fy  * gxc;
    float w111 = fz  * fy  * fx;

    int b00 = (iz0 * RESV + iy0) * RESV;
    int b01 = (iz0 * RESV + iy1) * RESV;
    int b10 = (iz1 * RESV + iy0) * RESV;
    int b11 = (iz1 * RESV + iy1) * RESV;

    const uint4* G = g_data64;
    uint4 a = __ldg(G + (((size_t)(b00 + ix0)) << 2) + sub);
    uint4 b = __ldg(G + (((size_t)(b00 + ix1)) << 2) + sub);
    uint4 c = __ldg(G + (((size_t)(b01 + ix0)) << 2) + sub);
    uint4 d = __ldg(G + (((size_t)(b01 + ix1)) << 2) + sub);
    uint4 e = __ldg(G + (((size_t)(b10 + ix0)) << 2) + sub);
    uint4 f = __ldg(G + (((size_t)(b10 + ix1)) << 2) + sub);
    uint4 h = __ldg(G + (((size_t)(b11 + ix0)) << 2) + sub);
    uint4 i = __ldg(G + (((size_t)(b11 + ix1)) << 2) + sub);

    float fa[8], fb[8], fc[8], fd[8], fe[8], ff[8], fh[8], fi[8];
    unpack8(a, fa); unpack8(b, fb); unpack8(c, fc); unpack8(d, fd);
    unpack8(e, fe); unpack8(f, ff); unpack8(h, fh); unpack8(i, fi);

    float r[8];
    #pragma unroll
    for (int k = 0; k < 8; k++) {
        r[k] = w000*fa[k] + w001*fb[k] + w010*fc[k] + w011*fd[k]
             + w100*fe[k] + w101*ff[k] + w110*fh[k] + w111*fi[k];
    }

    float4* op = (float4*)(data_out + (size_t)s * CHAN);
    __stcs(op + sub*2, make_float4(r[0], r[1], r[2], r[3]));
    if (sub < 3) {
        __stcs(op + sub*2 + 1, make_float4(r[4], r[5], r[6], r[7]));
    } else {
        float gx = (nx + 1.0f) * 64.0f;
        float gy = (ny + 1.0f) * 64.0f;
        float gz = (nz + 1.0f) * 64.0f;
        float gix = fminf(fmaxf(floorf(gx), 0.0f), 127.0f);
        float giy = fminf(fmaxf(floorf(gy), 0.0f), 127.0f);
        float giz = fminf(fmaxf(floorf(gz), 0.0f), 127.0f);
        __stcs(sub_out + (size_t)s*3+0, gx - gix);
        __stcs(sub_out + (size_t)s*3+1, gy - giy);
        __stcs(sub_out + (size_t)s*3+2, gz - giz);
    }
}

extern "C" void kernel_launch(void* const* d_in, const int* in_sizes, int n_in,
                              void* d_out, int out_size) {
    const float* rays_o = (const float*)d_in[0];
    const float* rays_d = (const float*)d_in[1];
    const float* data   = (const float*)d_in[2];
    float* out = (float*)d_out;

    const long long MASK_N = (long long)N_RAYS * NSAMP;    // 6,287,360
    const long long INTR_N = (long long)N_RAYS * N_INTERS; // 6,291,456
    long long nm = ((long long)out_size - MASK_N - INTR_N) / 31LL;

    float* data_out = out;
    float* mask_out = out + nm * CHAN;
    float* intr_out = mask_out + MASK_N;
    float* sub_out  = intr_out + INTR_N;

    k_scan2<<<1, 1024>>>(rays_o, rays_d);
    k_trmap<<<TR_BLOCKS + N_RAYS, 256>>>(data);

    long long nthreads = nm * 4;
    int nb_g = (int)((nthreads + 255) / 256);
    k_gather<<<N_RAYS + nb_g, 256>>>(data_out, sub_out, mask_out, intr_out, (int)nm);
}

// round 14
// speedup vs baseline: 1.2071x; 1.0442x over previous
#include <cuda_runtime.h>
#include <cuda_fp16.h>
#include <cuda_bf16.h>
#include <stdint.h>

#define N_RAYS   4096
#define N_INTERS 1536
#define NSAMP    1535          // N_INTERS - 1
#define RESV     128
#define CHAN     28
#define NVOX     (128*128*128)
#define CHSTRIDE NVOX
#define TR_BLOCKS (NVOX / 256)   // 8192 transpose blocks

__device__ int    g_ray_count[N_RAYS];
__device__ int    g_ray_base[N_RAYS + 1];   // exclusive scan + sentinel nm
__device__ int    g_map[(size_t)N_RAYS * NSAMP];   // oidx -> (ray<<11)|j
struct RayPack { float4 o_start; float4 d; };
__device__ RayPack g_raypack[N_RAYS];

// channel-last fp16 grid: voxel record = 28 halves + 4 pad = 64B = 4x uint4
__device__ uint4 g_data64[(size_t)NVOX * 4];

// --- mask-critical math: must be bit-stable under --use_fast_math ---
__device__ __forceinline__ float voxel_len() {
    return __fdiv_rn(__fsqrt_rn(27.0f), 1536.0f);
}

__device__ __forceinline__ float compute_start(float ox, float oy, float oz,
                                               float dx, float dy, float dz) {
    float px = __fdiv_rn(1.5f - ox, dx);
    float py = __fdiv_rn(1.5f - oy, dy);
    float pz = __fdiv_rn(1.5f - oz, dz);
    float nx = __fdiv_rn(-1.5f - ox, dx);
    float ny = __fdiv_rn(-1.5f - oy, dy);
    float nz = __fdiv_rn(-1.5f - oz, dz);
    float ix = fminf(px, nx);
    float iy = fminf(py, ny);
    float iz = fminf(pz, nz);
    float s  = fmaxf(fmaxf(ix, iy), iz);
    return fminf(fmaxf(s, 0.2f), 6.0f);
}

__device__ __forceinline__ float sample_t(float start, int j) {
    return __fadd_rn(start, __fmul_rn((float)j, voxel_len()));
}

__device__ __forceinline__ void point_at(float start, int j,
                                         float ox, float oy, float oz,
                                         float dx, float dy, float dz,
                                         float& px, float& py, float& pz) {
    float t = sample_t(start, j);
    px = __fadd_rn(ox, __fmul_rn(t, dx));
    py = __fadd_rn(oy, __fmul_rn(t, dy));
    pz = __fadd_rn(oz, __fmul_rn(t, dz));
}

__device__ __forceinline__ bool in_box(float px, float py, float pz) {
    return (-1.5f < px) & (px < 1.5f) &
           (-1.5f < py) & (py < 1.5f) &
           (-1.5f < pz) & (pz < 1.5f);
}

// exact mask predicate for (ray params, j) -- bit-identical to the original mask pass
__device__ __forceinline__ bool pred(float start, int j,
                                     float ox, float oy, float oz,
                                     float dx, float dy, float dz) {
    float px, py, pz;
    point_at(start, j, ox, oy, oz, dx, dy, dz, px, py, pz);
    return in_box(px, py, pz);
}

// unpack 8 halves (uint4) into 8 floats
__device__ __forceinline__ void unpack8(uint4 u, float* f) {
    float2 t;
    t = __half22float2(*reinterpret_cast<__half2*>(&u.x)); f[0]=t.x; f[1]=t.y;
    t = __half22float2(*reinterpret_cast<__half2*>(&u.y)); f[2]=t.x; f[3]=t.y;
    t = __half22float2(*reinterpret_cast<__half2*>(&u.z)); f[4]=t.x; f[5]=t.y;
    t = __half22float2(*reinterpret_cast<__half2*>(&u.w)); f[6]=t.x; f[7]=t.y;
}

// ============ Kernel 0: parallel per-ray start + exact cnt ===========================
__global__ void __launch_bounds__(256)
k_count(const float* __restrict__ rays_o, const float* __restrict__ rays_d) {
    int ray = blockIdx.x * 256 + threadIdx.x;
    if (ray >= N_RAYS) return;

    float ox = rays_o[ray*3+0], oy = rays_o[ray*3+1], oz = rays_o[ray*3+2];
    float dx = rays_d[ray*3+0], dy = rays_d[ray*3+1], dz = rays_d[ray*3+2];
    float start = compute_start(ox, oy, oz, dx, dy, dz);

    RayPack rp;
    rp.o_start = make_float4(ox, oy, oz, start);
    rp.d       = make_float4(dx, dy, dz, 0.0f);
    g_raypack[ray] = rp;

    // analytic exit-time estimate (tolerant math; exact refinement below)
    float te = 1e30f;
    if (dx > 0.0f) te = fminf(te, (1.5f - ox) / dx);
    else if (dx < 0.0f) te = fminf(te, (-1.5f - ox) / dx);
    if (dy > 0.0f) te = fminf(te, (1.5f - oy) / dy);
    else if (dy < 0.0f) te = fminf(te, (-1.5f - oy) / dy);
    if (dz > 0.0f) te = fminf(te, (1.5f - oz) / dz);
    else if (dz < 0.0f) te = fminf(te, (-1.5f - oz) / dz);

    float fj = (te - start) / voxel_len();
    int j = (fj < 0.0f) ? 0 : ((fj > (float)NSAMP) ? NSAMP : (int)fj);
    // exact refinement using the bit-exact predicate (mask is a j-prefix)
    while (j > 0 && !pred(start, j - 1, ox, oy, oz, dx, dy, dz)) j--;
    while (j < NSAMP && pred(start, j, ox, oy, oz, dx, dy, dz)) j++;
    g_ray_count[ray] = j;
}

// ============ Kernel 1: exclusive scan over 4096 ray counts ==========================
__global__ void __launch_bounds__(1024)
k_scan() {
    __shared__ int sh[1024];
    int tid = threadIdx.x;
    int c0 = g_ray_count[tid*4+0];
    int c1 = g_ray_count[tid*4+1];
    int c2 = g_ray_count[tid*4+2];
    int c3 = g_ray_count[tid*4+3];
    int tot = c0 + c1 + c2 + c3;
    sh[tid] = tot;
    __syncthreads();
    for (int off = 1; off < 1024; off <<= 1) {
        int v = (tid >= off) ? sh[tid - off] : 0;
        __syncthreads();
        sh[tid] += v;
        __syncthreads();
    }
    int excl = sh[tid] - tot;
    g_ray_base[tid*4+0] = excl;
    g_ray_base[tid*4+1] = excl + c0;
    g_ray_base[tid*4+2] = excl + c0 + c1;
    g_ray_base[tid*4+3] = excl + c0 + c1 + c2;
    if (tid == 1023) g_ray_base[N_RAYS] = sh[1023];   // sentinel = nm
}

// ============ Kernel 2 (fused): transpose->fp16  +  build_map =======================
__global__ void __launch_bounds__(256)
k_trmap(const float* __restrict__ data) {
    int tid = threadIdx.x;

    if (blockIdx.x < TR_BLOCKS) {
        __shared__ float tile[28][257];
        int v0 = blockIdx.x * 256;
        #pragma unroll
        for (int c = 0; c < 28; c++)
            tile[c][tid] = __ldg(data + (size_t)c * CHSTRIDE + v0 + tid);
        __syncthreads();
        uint2* out = (uint2*)g_data64;   // 8 uint2 per voxel, write all 8 (full 64B lines)
        #pragma unroll
        for (int k = 0; k < 8; k++) {
            int l  = k * 256 + tid;
            int v  = l >> 3;
            int c4 = l & 7;
            uint2 u;
            if (c4 < 7) {
                __half2 h0 = __floats2half2_rn(tile[4*c4+0][v], tile[4*c4+1][v]);
                __half2 h1 = __floats2half2_rn(tile[4*c4+2][v], tile[4*c4+3][v]);
                u.x = *reinterpret_cast<unsigned*>(&h0);
                u.y = *reinterpret_cast<unsigned*>(&h1);
            } else {
                u.x = 0u; u.y = 0u;
            }
            out[(size_t)(v0 + v) * 8 + c4] = u;
        }
        return;
    }

    // build_map path
    int ray  = blockIdx.x - TR_BLOCKS;
    int base = __ldg(&g_ray_base[ray]);
    int cnt  = __ldg(&g_ray_base[ray + 1]) - base;
    int tag  = ray << 11;
    for (int j = tid; j < cnt; j += 256)
        g_map[base + j] = tag | j;
}

// ============ Kernel 3 (fused): mask/intersections blocks + flat gather ==============
__global__ void __launch_bounds__(256)
k_gather(float* __restrict__ data_out, float* __restrict__ sub_out,
         float* __restrict__ mask_out, float* __restrict__ intr_out, int nm) {
    int tid = threadIdx.x;

    if (blockIdx.x < N_RAYS) {
        // -------- mask + intersections path (pure stores; cnt from scan) --------
        int ray  = blockIdx.x;
        int base = __ldg(&g_ray_base[ray]);
        int cnt  = __ldg(&g_ray_base[ray + 1]) - base;
        float start = __ldg(&g_raypack[ray].o_start).w;
        for (int j = tid; j < N_INTERS; j += 256)
            __stcs(intr_out + (size_t)ray * N_INTERS + j, sample_t(start, j));
        for (int j = tid; j < NSAMP; j += 256)
            __stcs(mask_out + (size_t)ray * NSAMP + j, (j < cnt) ? 1.0f : 0.0f);
        return;
    }

    // -------- flat gather: 4 lanes per sample (R9-proven body) --------
    int gt = (blockIdx.x - N_RAYS) * 256 + tid;
    int s   = gt >> 2;
    int sub = gt & 3;
    if (s >= nm) return;

    int info = __ldg(&g_map[s]);
    int ray = info >> 11;
    int j   = info & 2047;

    float4 osr = __ldg(&g_raypack[ray].o_start);
    float4 dd  = __ldg(&g_raypack[ray].d);

    float px, py, pz;
    point_at(osr.w, j, osr.x, osr.y, osr.z, dd.x, dd.y, dd.z, px, py, pz);

    const float INV = 0.66666668653f;  // float(2/3)
    float nx = (px + 1.5f) * INV - 1.0f;
    float ny = (py + 1.5f) * INV - 1.0f;
    float nz = (pz + 1.5f) * INV - 1.0f;

    float x = (nx + 1.0f) * 63.5f;
    float y = (ny + 1.0f) * 63.5f;
    float z = (nz + 1.0f) * 63.5f;
    float x0f = floorf(x), y0f = floorf(y), z0f = floorf(z);
    float fx = x - x0f, fy = y - y0f, fz = z - z0f;
    int ix0 = min(max((int)x0f, 0), 127);
    int iy0 = min(max((int)y0f, 0), 127);
    int iz0 = min(max((int)z0f, 0), 127);
    int ix1 = min(ix0 + 1, 127);
    int iy1 = min(iy0 + 1, 127);
    int iz1 = min(iz0 + 1, 127);

    float gxc = 1.0f - fx, gyc = 1.0f - fy, gzc = 1.0f - fz;
    float w000 = gzc * gyc * gxc;
    float w001 = gzc * gyc * fx;
    float w010 = gzc * fy  * gxc;
    float w011 = gzc * fy  * fx;
    float w100 = fz  * gyc * gxc;
    float w101 = fz  * gyc * fx;
    float w110 = fz  * fy  * gxc;
    float w111 = fz  * fy  * fx;

    int b00 = (iz0 * RESV + iy0) * RESV;
    int b01 = (iz0 * RESV + iy1) * RESV;
    int b10 = (iz1 * RESV + iy0) * RESV;
    int b11 = (iz1 * RESV + iy1) * RESV;

    const uint4* G = g_data64;
    uint4 a = __ldg(G + (((size_t)(b00 + ix0)) << 2) + sub);
    uint4 b = __ldg(G + (((size_t)(b00 + ix1)) << 2) + sub);
    uint4 c = __ldg(G + (((size_t)(b01 + ix0)) << 2) + sub);
    uint4 d = __ldg(G + (((size_t)(b01 + ix1)) << 2) + sub);
    uint4 e = __ldg(G + (((size_t)(b10 + ix0)) << 2) + sub);
    uint4 f = __ldg(G + (((size_t)(b10 + ix1)) << 2) + sub);
    uint4 h = __ldg(G + (((size_t)(b11 + ix0)) << 2) + sub);
    uint4 i = __ldg(G + (((size_t)(b11 + ix1)) << 2) + sub);

    float fa[8], fb[8], fc[8], fd[8], fe[8], ff[8], fh[8], fi[8];
    unpack8(a, fa); unpack8(b, fb); unpack8(c, fc); unpack8(d, fd);
    unpack8(e, fe); unpack8(f, ff); unpack8(h, fh); unpack8(i, fi);

    float r[8];
    #pragma unroll
    for (int k = 0; k < 8; k++) {
        r[k] = w000*fa[k] + w001*fb[k] + w010*fc[k] + w011*fd[k]
             + w100*fe[k] + w101*ff[k] + w110*fh[k] + w111*fi[k];
    }

    float4* op = (float4*)(data_out + (size_t)s * CHAN);
    __stcs(op + sub*2, make_float4(r[0], r[1], r[2], r[3]));
    if (sub < 3) {
        __stcs(op + sub*2 + 1, make_float4(r[4], r[5], r[6], r[7]));
    } else {
        float gx = (nx + 1.0f) * 64.0f;
        float gy = (ny + 1.0f) * 64.0f;
        float gz = (nz + 1.0f) * 64.0f;
        float gix = fminf(fmaxf(floorf(gx), 0.0f), 127.0f);
        float giy = fminf(fmaxf(floorf(gy), 0.0f), 127.0f);
        float giz = fminf(fmaxf(floorf(gz), 0.0f), 127.0f);
        __stcs(sub_out + (size_t)s*3+0, gx - gix);
        __stcs(sub_out + (size_t)s*3+1, gy - giy);
        __stcs(sub_out + (size_t)s*3+2, gz - giz);
    }
}

extern "C" void kernel_launch(void* const* d_in, const int* in_sizes, int n_in,
                              void* d_out, int out_size) {
    const float* rays_o = (const float*)d_in[0];
    const float* rays_d = (const float*)d_in[1];
    const float* data   = (const float*)d_in[2];
    float* out = (float*)d_out;

    const long long MASK_N = (long long)N_RAYS * NSAMP;    // 6,287,360
    const long long INTR_N = (long long)N_RAYS * N_INTERS; // 6,291,456
    long long nm = ((long long)out_size - MASK_N - INTR_N) / 31LL;

    float* data_out = out;
    float* mask_out = out + nm * CHAN;
    float* intr_out = mask_out + MASK_N;
    float* sub_out  = intr_out + INTR_N;

    k_count<<<N_RAYS / 256, 256>>>(rays_o, rays_d);
    k_scan<<<1, 1024>>>();
    k_trmap<<<TR_BLOCKS + N_RAYS, 256>>>(data);

    long long nthreads = nm * 4;
    int nb_g = (int)((nthreads + 255) / 256);
    k_gather<<<N_RAYS + nb_g, 256>>>(data_out, sub_out, mask_out, intr_out, (int)nm);
}

// round 15
// speedup vs baseline: 1.2619x; 1.0454x over previous
#include <cuda_runtime.h>
#include <cuda_fp16.h>
#include <cuda_bf16.h>
#include <stdint.h>

#define N_RAYS   4096
#define N_INTERS 1536
#define NSAMP    1535          // N_INTERS - 1
#define RESV     128
#define CHAN     28
#define NVOX     (128*128*128)
#define CHSTRIDE NVOX
#define TR_BLOCKS (NVOX / 256)   // 8192 transpose blocks

__device__ int    g_ray_count[N_RAYS];
__device__ int    g_ray_base[N_RAYS + 1];   // exclusive scan + sentinel nm
// per-sample descriptor: .x = v000 | sx<<21 | sy<<22 | sz<<23 ; .y/.z/.w = fx/fy/fz bits
__device__ uint4  g_mapv[(size_t)N_RAYS * NSAMP];
struct RayPack { float4 o_start; float4 d; };
__device__ RayPack g_raypack[N_RAYS];

// channel-last fp16 grid: voxel record = 28 halves + 4 pad = 64B = 4x uint4
__device__ uint4 g_data64[(size_t)NVOX * 4];

// --- mask-critical math: must be bit-stable under --use_fast_math ---
__device__ __forceinline__ float voxel_len() {
    return __fdiv_rn(__fsqrt_rn(27.0f), 1536.0f);
}

__device__ __forceinline__ float compute_start(float ox, float oy, float oz,
                                               float dx, float dy, float dz) {
    float px = __fdiv_rn(1.5f - ox, dx);
    float py = __fdiv_rn(1.5f - oy, dy);
    float pz = __fdiv_rn(1.5f - oz, dz);
    float nx = __fdiv_rn(-1.5f - ox, dx);
    float ny = __fdiv_rn(-1.5f - oy, dy);
    float nz = __fdiv_rn(-1.5f - oz, dz);
    float ix = fminf(px, nx);
    float iy = fminf(py, ny);
    float iz = fminf(pz, nz);
    float s  = fmaxf(fmaxf(ix, iy), iz);
    return fminf(fmaxf(s, 0.2f), 6.0f);
}

__device__ __forceinline__ float sample_t(float start, int j) {
    return __fadd_rn(start, __fmul_rn((float)j, voxel_len()));
}

__device__ __forceinline__ void point_at(float start, int j,
                                         float ox, float oy, float oz,
                                         float dx, float dy, float dz,
                                         float& px, float& py, float& pz) {
    float t = sample_t(start, j);
    px = __fadd_rn(ox, __fmul_rn(t, dx));
    py = __fadd_rn(oy, __fmul_rn(t, dy));
    pz = __fadd_rn(oz, __fmul_rn(t, dz));
}

__device__ __forceinline__ bool in_box(float px, float py, float pz) {
    return (-1.5f < px) & (px < 1.5f) &
           (-1.5f < py) & (py < 1.5f) &
           (-1.5f < pz) & (pz < 1.5f);
}

// exact mask predicate (bit-identical to the original mask pass)
__device__ __forceinline__ bool pred(float start, int j,
                                     float ox, float oy, float oz,
                                     float dx, float dy, float dz) {
    float px, py, pz;
    point_at(start, j, ox, oy, oz, dx, dy, dz, px, py, pz);
    return in_box(px, py, pz);
}

// unpack 8 halves (uint4) into 8 floats
__device__ __forceinline__ void unpack8(uint4 u, float* f) {
    float2 t;
    t = __half22float2(*reinterpret_cast<__half2*>(&u.x)); f[0]=t.x; f[1]=t.y;
    t = __half22float2(*reinterpret_cast<__half2*>(&u.y)); f[2]=t.x; f[3]=t.y;
    t = __half22float2(*reinterpret_cast<__half2*>(&u.z)); f[4]=t.x; f[5]=t.y;
    t = __half22float2(*reinterpret_cast<__half2*>(&u.w)); f[6]=t.x; f[7]=t.y;
}

// ============ Kernel 0: parallel per-ray start + exact cnt ===========================
__global__ void __launch_bounds__(256)
k_count(const float* __restrict__ rays_o, const float* __restrict__ rays_d) {
    int ray = blockIdx.x * 256 + threadIdx.x;
    if (ray >= N_RAYS) return;

    float ox = rays_o[ray*3+0], oy = rays_o[ray*3+1], oz = rays_o[ray*3+2];
    float dx = rays_d[ray*3+0], dy = rays_d[ray*3+1], dz = rays_d[ray*3+2];
    float start = compute_start(ox, oy, oz, dx, dy, dz);

    RayPack rp;
    rp.o_start = make_float4(ox, oy, oz, start);
    rp.d       = make_float4(dx, dy, dz, 0.0f);
    g_raypack[ray] = rp;

    float te = 1e30f;
    if (dx > 0.0f) te = fminf(te, (1.5f - ox) / dx);
    else if (dx < 0.0f) te = fminf(te, (-1.5f - ox) / dx);
    if (dy > 0.0f) te = fminf(te, (1.5f - oy) / dy);
    else if (dy < 0.0f) te = fminf(te, (-1.5f - oy) / dy);
    if (dz > 0.0f) te = fminf(te, (1.5f - oz) / dz);
    else if (dz < 0.0f) te = fminf(te, (-1.5f - oz) / dz);

    float fj = (te - start) / voxel_len();
    int j = (fj < 0.0f) ? 0 : ((fj > (float)NSAMP) ? NSAMP : (int)fj);
    while (j > 0 && !pred(start, j - 1, ox, oy, oz, dx, dy, dz)) j--;
    while (j < NSAMP && pred(start, j, ox, oy, oz, dx, dy, dz)) j++;
    g_ray_count[ray] = j;
}

// ============ Kernel 1: exclusive scan over 4096 ray counts ==========================
__global__ void __launch_bounds__(1024)
k_scan() {
    __shared__ int sh[1024];
    int tid = threadIdx.x;
    int c0 = g_ray_count[tid*4+0];
    int c1 = g_ray_count[tid*4+1];
    int c2 = g_ray_count[tid*4+2];
    int c3 = g_ray_count[tid*4+3];
    int tot = c0 + c1 + c2 + c3;
    sh[tid] = tot;
    __syncthreads();
    for (int off = 1; off < 1024; off <<= 1) {
        int v = (tid >= off) ? sh[tid - off] : 0;
        __syncthreads();
        sh[tid] += v;
        __syncthreads();
    }
    int excl = sh[tid] - tot;
    g_ray_base[tid*4+0] = excl;
    g_ray_base[tid*4+1] = excl + c0;
    g_ray_base[tid*4+2] = excl + c0 + c1;
    g_ray_base[tid*4+3] = excl + c0 + c1 + c2;
    if (tid == 1023) g_ray_base[N_RAYS] = sh[1023];   // sentinel = nm
}

// ============ Kernel 2 (fused): transpose->fp16  +  descriptor map + sub_pts ========
__global__ void __launch_bounds__(256)
k_trmap(const float* __restrict__ data, float* __restrict__ sub_out) {
    int tid = threadIdx.x;

    if (blockIdx.x < TR_BLOCKS) {
        __shared__ float tile[28][257];
        int v0 = blockIdx.x * 256;
        #pragma unroll
        for (int c = 0; c < 28; c++)
            tile[c][tid] = __ldg(data + (size_t)c * CHSTRIDE + v0 + tid);
        __syncthreads();
        uint2* out = (uint2*)g_data64;   // 8 uint2 per voxel, write all 8 (full 64B lines)
        #pragma unroll
        for (int k = 0; k < 8; k++) {
            int l  = k * 256 + tid;
            int v  = l >> 3;
            int c4 = l & 7;
            uint2 u;
            if (c4 < 7) {
                __half2 h0 = __floats2half2_rn(tile[4*c4+0][v], tile[4*c4+1][v]);
                __half2 h1 = __floats2half2_rn(tile[4*c4+2][v], tile[4*c4+3][v]);
                u.x = *reinterpret_cast<unsigned*>(&h0);
                u.y = *reinterpret_cast<unsigned*>(&h1);
            } else {
                u.x = 0u; u.y = 0u;
            }
            out[(size_t)(v0 + v) * 8 + c4] = u;
        }
        return;
    }

    // ---- descriptor-map path: one ray per block ----
    int ray  = blockIdx.x - TR_BLOCKS;
    int base = __ldg(&g_ray_base[ray]);
    int cnt  = __ldg(&g_ray_base[ray + 1]) - base;
    float4 osr = __ldg(&g_raypack[ray].o_start);
    float4 dd  = __ldg(&g_raypack[ray].d);

    const float INV = 0.66666668653f;  // float(2/3)

    for (int j = tid; j < cnt; j += 256) {
        float px, py, pz;
        point_at(osr.w, j, osr.x, osr.y, osr.z, dd.x, dd.y, dd.z, px, py, pz);
        float nx = (px + 1.5f) * INV - 1.0f;
        float ny = (py + 1.5f) * INV - 1.0f;
        float nz = (pz + 1.5f) * INV - 1.0f;

        int s = base + j;

        // sub_pts (same formulas as before)
        float gx = (nx + 1.0f) * 64.0f;
        float gy = (ny + 1.0f) * 64.0f;
        float gz = (nz + 1.0f) * 64.0f;
        float gix = fminf(fmaxf(floorf(gx), 0.0f), 127.0f);
        float giy = fminf(fmaxf(floorf(gy), 0.0f), 127.0f);
        float giz = fminf(fmaxf(floorf(gz), 0.0f), 127.0f);
        __stcs(sub_out + (size_t)s*3+0, gx - gix);
        __stcs(sub_out + (size_t)s*3+1, gy - giy);
        __stcs(sub_out + (size_t)s*3+2, gz - giz);

        // trilinear descriptor (same formulas as before)
        float x = (nx + 1.0f) * 63.5f;
        float y = (ny + 1.0f) * 63.5f;
        float z = (nz + 1.0f) * 63.5f;
        float x0f = floorf(x), y0f = floorf(y), z0f = floorf(z);
        float fx = x - x0f, fy = y - y0f, fz = z - z0f;
        int ix0 = min(max((int)x0f, 0), 127);
        int iy0 = min(max((int)y0f, 0), 127);
        int iz0 = min(max((int)z0f, 0), 127);
        int sx = (ix0 < 127) ? 1 : 0;
        int sy = (iy0 < 127) ? 1 : 0;
        int sz = (iz0 < 127) ? 1 : 0;

        uint4 ent;
        ent.x = (unsigned)((iz0 * RESV + iy0) * RESV + ix0)
              | ((unsigned)sx << 21) | ((unsigned)sy << 22) | ((unsigned)sz << 23);
        ent.y = __float_as_uint(fx);
        ent.z = __float_as_uint(fy);
        ent.w = __float_as_uint(fz);
        g_mapv[s] = ent;
    }
}

// ============ Kernel 3 (fused): mask/intersections blocks + flat gather ==============
__global__ void __launch_bounds__(256)
k_gather(float* __restrict__ data_out,
         float* __restrict__ mask_out, float* __restrict__ intr_out, int nm) {
    int tid = threadIdx.x;

    if (blockIdx.x < N_RAYS) {
        int ray  = blockIdx.x;
        int base = __ldg(&g_ray_base[ray]);
        int cnt  = __ldg(&g_ray_base[ray + 1]) - base;
        float start = __ldg(&g_raypack[ray].o_start).w;
        for (int j = tid; j < N_INTERS; j += 256)
            __stcs(intr_out + (size_t)ray * N_INTERS + j, sample_t(start, j));
        for (int j = tid; j < NSAMP; j += 256)
            __stcs(mask_out + (size_t)ray * NSAMP + j, (j < cnt) ? 1.0f : 0.0f);
        return;
    }

    // -------- flat gather: 4 lanes per sample, precomputed descriptor --------
    int gt = (blockIdx.x - N_RAYS) * 256 + tid;
    int s   = gt >> 2;
    int sub = gt & 3;
    if (s >= nm) return;

    uint4 ent = __ldg(&g_mapv[s]);
    int v000 = ent.x & 0x1FFFFF;
    int vx   = (ent.x >> 21) & 1;          // +1 in x (or 0 at edge)
    int vy   = ((ent.x >> 22) & 1) << 7;   // +128 in y
    int vz   = ((ent.x >> 23) & 1) << 14;  // +16384 in z
    float fx = __uint_as_float(ent.y);
    float fy = __uint_as_float(ent.z);
    float fz = __uint_as_float(ent.w);

    float gxc = 1.0f - fx, gyc = 1.0f - fy, gzc = 1.0f - fz;
    float w000 = gzc * gyc * gxc;
    float w001 = gzc * gyc * fx;
    float w010 = gzc * fy  * gxc;
    float w011 = gzc * fy  * fx;
    float w100 = fz  * gyc * gxc;
    float w101 = fz  * gyc * fx;
    float w110 = fz  * fy  * gxc;
    float w111 = fz  * fy  * fx;

    const uint4* G = g_data64;
    uint4 a = __ldg(G + (((size_t)(v000          )) << 2) + sub);
    uint4 b = __ldg(G + (((size_t)(v000 + vx     )) << 2) + sub);
    uint4 c = __ldg(G + (((size_t)(v000 + vy     )) << 2) + sub);
    uint4 d = __ldg(G + (((size_t)(v000 + vy + vx)) << 2) + sub);
    uint4 e = __ldg(G + (((size_t)(v000 + vz     )) << 2) + sub);
    uint4 f = __ldg(G + (((size_t)(v000 + vz + vx)) << 2) + sub);
    uint4 h = __ldg(G + (((size_t)(v000 + vz + vy)) << 2) + sub);
    uint4 i = __ldg(G + (((size_t)(v000 + vz + vy + vx)) << 2) + sub);

    float fa[8], fb[8], fc[8], fd[8], fe[8], ff[8], fh[8], fi[8];
    unpack8(a, fa); unpack8(b, fb); unpack8(c, fc); unpack8(d, fd);
    unpack8(e, fe); unpack8(f, ff); unpack8(h, fh); unpack8(i, fi);

    float r[8];
    #pragma unroll
    for (int k = 0; k < 8; k++) {
        r[k] = w000*fa[k] + w001*fb[k] + w010*fc[k] + w011*fd[k]
             + w100*fe[k] + w101*ff[k] + w110*fh[k] + w111*fi[k];
    }

    float4* op = (float4*)(data_out + (size_t)s * CHAN);
    __stcs(op + sub*2, make_float4(r[0], r[1], r[2], r[3]));
    if (sub < 3)
        __stcs(op + sub*2 + 1, make_float4(r[4], r[5], r[6], r[7]));
}

extern "C" void kernel_launch(void* const* d_in, const int* in_sizes, int n_in,
                              void* d_out, int out_size) {
    const float* rays_o = (const float*)d_in[0];
    const float* rays_d = (const float*)d_in[1];
    const float* data   = (const float*)d_in[2];
    float* out = (float*)d_out;

    const long long MASK_N = (long long)N_RAYS * NSAMP;    // 6,287,360
    const long long INTR_N = (long long)N_RAYS * N_INTERS; // 6,291,456
    long long nm = ((long long)out_size - MASK_N - INTR_N) / 31LL;

    float* data_out = out;
    float* mask_out = out + nm * CHAN;
    float* intr_out = mask_out + MASK_N;
    float* sub_out  = intr_out + INTR_N;

    k_count<<<N_RAYS / 256, 256>>>(rays_o, rays_d);
    k_scan<<<1, 1024>>>();
    k_trmap<<<TR_BLOCKS + N_RAYS, 256>>>(data, sub_out);

    long long nthreads = nm * 4;
    int nb_g = (int)((nthreads + 255) / 256);
    k_gather<<<N_RAYS + nb_g, 256>>>(data_out, mask_out, intr_out, (int)nm);
}